// round 7
// baseline (speedup 1.0000x reference)
#include <cuda_runtime.h>
#include <cuda_bf16.h>

// Problem constants
#define HW_N   262144      // H*W
#define KN     512         // num_embeddings
#define DN     64          // embedding_dim
#define EMA_D  0.99f
#define EPS    1e-5f

// Output layout (reference return order, all fp32):
#define O_ZQ    0               // z_q_st   [H,W,D] 16777216
#define O_IDX   16777216        // indices  [H,W]     262144
#define O_MIND  17039360        // min_dist [N]       262144
#define O_CB    17301504        // new_codebook [K,D]  32768
#define O_CS    17334272        // new_ema_cluster [K]   512
#define O_SUM   17334784        // new_ema_emb_sum [K,D] 32768

// Scratch (no cudaMalloc allowed) — zeroed every launch by init kernel.
__device__ float g_counts[KN];
__device__ float g_sums[KN * DN];
__device__ float g_bsq[KN];

// packed fp32x2 FMA (SASS FFMA2) — 2x fp32 throughput (approx path only)
__device__ __forceinline__ unsigned long long fma2(unsigned long long a,
                                                   unsigned long long b,
                                                   unsigned long long c) {
    unsigned long long d;
    asm("fma.rn.f32x2 %0, %1, %2, %3;" : "=l"(d) : "l"(a), "l"(b), "l"(c));
    return d;
}

__device__ __forceinline__ float sum2(unsigned long long a) {
    unsigned int lo, hi;
    asm("mov.b64 {%0, %1}, %2;" : "=r"(lo), "=r"(hi) : "l"(a));
    return __uint_as_float(lo) + __uint_as_float(hi);
}

// ---------------------------------------------------------------------------
// Kernel 1: zero scratch + codebook squared norms.
// b_sq: strict sequential s = rn(s + rn(c*c)) (b_sq order is sub-grid
// irrelevant to the decision; any consistent fp32 order suffices).
// ---------------------------------------------------------------------------
__global__ void vq_init_kernel(const float* __restrict__ cb) {
    int t = blockIdx.x * blockDim.x + threadIdx.x;   // 64*512 = 32768 threads
    if (t < KN * DN) g_sums[t] = 0.0f;
    if (t < KN) {
        g_counts[t] = 0.0f;
        const float* row = cb + t * DN;
        float s = 0.0f;
#pragma unroll
        for (int d = 0; d < DN; d++)
            s = __fadd_rn(s, __fmul_rn(row[d], row[d]));
        g_bsq[t] = s;
    }
}

// ---------------------------------------------------------------------------
// Kernel 2: distances + top-2 argmin + exact recheck + z_q + EMA scatter
//   Block: 256 threads = 8 (k-lanes) x 32 (point-lanes). 128 points/block.
//   Fast path: f32x2 FMA microtile (4pt x 4code), codebook chunks of 32
//   streamed through smem with register prefetch.
//   Exact path: top-2 finalists re-evaluated with reference arithmetic.
// ---------------------------------------------------------------------------
#define ZS 68   // smem row stride in floats (16B aligned, conflict-free)

__global__ __launch_bounds__(256)
void vq_main_kernel(const float* __restrict__ z_e,
                    const float* __restrict__ cb,
                    float* __restrict__ out) {
    __shared__ float z_sm[128 * ZS];   // 34816 B
    __shared__ float c_sm[32 * ZS];    //  8704 B
    __shared__ float asq_sm[128];
    __shared__ float bsq_sm[32];
    __shared__ int   idx_sm[128];
    __shared__ int   c1_sm[128];       // top-2 candidate indices per point
    __shared__ int   c2_sm[128];

    const int tid = threadIdx.x;
    const int tx  = tid & 7;     // k-lane (0..7)
    const int ty  = tid >> 3;    // point-lane (0..31)
    const int pbase = blockIdx.x * 128;

    // this thread's 2 float4 slots within a 32-row codebook chunk
    const int cr0 = tid >> 4;            // rows 0..15
    const int cc0 = (tid & 15) * 4;      // float offset 0..60
    const int cr1 = cr0 + 16;            // rows 16..31

    // ---- load 128x64 z tile
#pragma unroll
    for (int i = 0; i < 8; i++) {
        int e   = tid + i * 256;         // 0..2047 float4 slots
        int row = e >> 4;
        int c4  = e & 15;
        float4 v = *(const float4*)(z_e + (size_t)(pbase + row) * DN + c4 * 4);
        *(float4*)&z_sm[row * ZS + c4 * 4] = v;
    }

    // ---- prefetch codebook chunk 0
    float4 pf0 = *(const float4*)(cb + (size_t)cr0 * DN + cc0);
    float4 pf1 = *(const float4*)(cb + (size_t)cr1 * DN + cc0);
    float  pfb = (tid < 32) ? g_bsq[tid] : 0.0f;

    __syncthreads();

    // ---- a_sq: sequential rn(s + rn(v*v)); order shifts are common-mode
    // across candidates -> argmin-invariant (see analysis)
    if (tid < 128) {
        float s = 0.0f;
#pragma unroll
        for (int d = 0; d < DN; d++) {
            float v = z_sm[tid * ZS + d];
            s = __fadd_rn(s, __fmul_rn(v, v));
        }
        asq_sm[tid] = s;
    }

    // top-2 tracking per point (approx values, index tie-break)
    float v1[4], v2[4];
    int   i1[4], i2[4];
#pragma unroll
    for (int pp = 0; pp < 4; pp++) {
        v1[pp] = 3.4e38f; v2[pp] = 3.4e38f; i1[pp] = KN; i2[pp] = KN;
    }

    for (int chunk = 0; chunk < KN / 32; chunk++) {
        // commit prefetched chunk to smem
        *(float4*)&c_sm[cr0 * ZS + cc0] = pf0;
        *(float4*)&c_sm[cr1 * ZS + cc0] = pf1;
        if (tid < 32) bsq_sm[tid] = pfb;
        __syncthreads();

        // prefetch next chunk while this one is consumed
        if (chunk + 1 < KN / 32) {
            const float* cbn = cb + (size_t)(chunk + 1) * 32 * DN;
            pf0 = *(const float4*)(cbn + (size_t)cr0 * DN + cc0);
            pf1 = *(const float4*)(cbn + (size_t)cr1 * DN + cc0);
            if (tid < 32) pfb = g_bsq[(chunk + 1) * 32 + tid];
        }

        unsigned long long acc[4][4];
#pragma unroll
        for (int pp = 0; pp < 4; pp++)
#pragma unroll
            for (int kk = 0; kk < 4; kk++) acc[pp][kk] = 0ULL;

#pragma unroll
        for (int d4 = 0; d4 < DN / 4; d4++) {
            ulonglong2 zv[4], cv[4];
#pragma unroll
            for (int pp = 0; pp < 4; pp++)
                zv[pp] = *(const ulonglong2*)&z_sm[(pp * 32 + ty) * ZS + d4 * 4];
#pragma unroll
            for (int kk = 0; kk < 4; kk++)
                cv[kk] = *(const ulonglong2*)&c_sm[(kk * 8 + tx) * ZS + d4 * 4];
#pragma unroll
            for (int pp = 0; pp < 4; pp++)
#pragma unroll
                for (int kk = 0; kk < 4; kk++) {
                    acc[pp][kk] = fma2(zv[pp].x, cv[kk].x, acc[pp][kk]);
                    acc[pp][kk] = fma2(zv[pp].y, cv[kk].y, acc[pp][kk]);
                }
        }

        // ---- top-2 update (approx vals; ascending k preserves ties-by-index)
#pragma unroll
        for (int kk = 0; kk < 4; kk++) {
            int kloc = kk * 8 + tx;
            int kg   = chunk * 32 + kloc;
            float b  = bsq_sm[kloc];
#pragma unroll
            for (int pp = 0; pp < 4; pp++) {
                float val = fmaf(-2.0f, sum2(acc[pp][kk]), b);
                if (val < v1[pp]) {
                    v2[pp] = v1[pp]; i2[pp] = i1[pp];
                    v1[pp] = val;    i1[pp] = kg;
                } else if (val < v2[pp]) {
                    v2[pp] = val;    i2[pp] = kg;
                }
            }
        }
        __syncthreads();
    }

    // ---- merge top-2 across the 8 k-lanes (xor shuffles within 8-lane groups)
#pragma unroll
    for (int off = 4; off >= 1; off >>= 1) {
#pragma unroll
        for (int pp = 0; pp < 4; pp++) {
            float ov1 = __shfl_xor_sync(0xFFFFFFFFu, v1[pp], off);
            int   oi1 = __shfl_xor_sync(0xFFFFFFFFu, i1[pp], off);
            float ov2 = __shfl_xor_sync(0xFFFFFFFFu, v2[pp], off);
            int   oi2 = __shfl_xor_sync(0xFFFFFFFFu, i2[pp], off);
            if (ov1 < v1[pp] || (ov1 == v1[pp] && oi1 < i1[pp])) {
                // other's best wins; second = better of (my best, other's 2nd)
                float nv2; int ni2;
                if (v1[pp] < ov2 || (v1[pp] == ov2 && i1[pp] < oi2)) {
                    nv2 = v1[pp]; ni2 = i1[pp];
                } else { nv2 = ov2; ni2 = oi2; }
                v1[pp] = ov1; i1[pp] = oi1;
                v2[pp] = nv2; i2[pp] = ni2;
            } else if (ov1 < v2[pp] || (ov1 == v2[pp] && oi1 < i2[pp])) {
                v2[pp] = ov1; i2[pp] = oi1;
            }
        }
    }

    if (tx == 0) {
#pragma unroll
        for (int pp = 0; pp < 4; pp++) {
            int p = pp * 32 + ty;
            c1_sm[p] = i1[pp];
            c2_sm[p] = i2[pp];
        }
    }
    __syncthreads();

    // ---- exact recheck of the two finalists with reference arithmetic:
    //   dot  = sequential-k single-accumulator fmaf chain
    //          (Eigen gebp / cublas sgemm k-order, both backends)
    //   val  = rn(rn(a_sq - rn(2*dot)) + b_sq), ties -> lowest index
    if (tid < 128) {
        int p  = tid;
        int ca = c1_sm[p];
        int cb2 = c2_sm[p];
        float asq = asq_sm[p];
        const float* rowa = cb + (size_t)ca  * DN;
        const float* rowb = cb + (size_t)cb2 * DN;
        float da = 0.0f, db = 0.0f;
#pragma unroll
        for (int d = 0; d < DN; d++) {
            float z = z_sm[p * ZS + d];
            da = fmaf(z, __ldg(rowa + d), da);
            db = fmaf(z, __ldg(rowb + d), db);
        }
        float va = __fadd_rn(__fsub_rn(asq, __fmul_rn(2.0f, da)), g_bsq[ca]);
        float vb = __fadd_rn(__fsub_rn(asq, __fmul_rn(2.0f, db)), g_bsq[cb2]);
        int wi; float wv;
        if (vb < va || (vb == va && cb2 < ca)) { wi = cb2; wv = vb; }
        else                                    { wi = ca;  wv = va; }
        idx_sm[p] = wi;
        out[O_IDX  + pbase + p] = (float)wi;
        out[O_MIND + pbase + p] = wv;
        atomicAdd(&g_counts[wi], 1.0f);
    }
    __syncthreads();

    // ---- epilogue: z_q_st gather + embedding scatter-add (2 threads/point)
    {
        int p     = tid >> 1;
        int dbase = (tid & 1) * 32;
        int ci    = idx_sm[p];
        const float* crow = cb + (size_t)ci * DN;
        float* orow = out + O_ZQ + (size_t)(pbase + p) * DN;
        float* srow = g_sums + (size_t)ci * DN;
#pragma unroll
        for (int q = 0; q < 8; q++) {
            int d = dbase + q * 4;
            float4 c = *(const float4*)(crow + d);
            float4 z = *(const float4*)&z_sm[p * ZS + d];
            // straight-through: z + (z_q - z)  (match reference fp order)
            float4 r;
            r.x = __fadd_rn(z.x, __fsub_rn(c.x, z.x));
            r.y = __fadd_rn(z.y, __fsub_rn(c.y, z.y));
            r.z = __fadd_rn(z.z, __fsub_rn(c.z, z.z));
            r.w = __fadd_rn(z.w, __fsub_rn(c.w, z.w));
            *(float4*)(orow + d) = r;
            asm volatile("red.global.add.v4.f32 [%0], {%1, %2, %3, %4};"
                         :: "l"(srow + d), "f"(z.x), "f"(z.y), "f"(z.z), "f"(z.w)
                         : "memory");
        }
    }
}

// ---------------------------------------------------------------------------
// Kernel 3: EMA update + new codebook (exact rn ops)
// ---------------------------------------------------------------------------
__global__ void vq_final_kernel(const float* __restrict__ ema_cs,
                                const float* __restrict__ ema_sum,
                                float* __restrict__ out) {
    int k = blockIdx.x;      // 512 blocks
    int d = threadIdx.x;     // 64 threads
    float cs_new = __fadd_rn(__fmul_rn(EMA_D, ema_cs[k]),
                             __fmul_rn(1.0f - EMA_D, g_counts[k]));
    if (d == 0) out[O_CS + k] = cs_new;
    float s_new = __fadd_rn(__fmul_rn(EMA_D, ema_sum[k * DN + d]),
                            __fmul_rn(1.0f - EMA_D, g_sums[k * DN + d]));
    out[O_SUM + k * DN + d] = s_new;
    out[O_CB  + k * DN + d] = __fdiv_rn(s_new, __fadd_rn(cs_new, EPS));
}

// ---------------------------------------------------------------------------
extern "C" void kernel_launch(void* const* d_in, const int* in_sizes, int n_in,
                              void* d_out, int out_size) {
    const float* z_e      = (const float*)d_in[0];
    const float* codebook = (const float*)d_in[1];
    const float* ema_cs   = (const float*)d_in[2];
    const float* ema_sum  = (const float*)d_in[3];
    float* out = (float*)d_out;

    vq_init_kernel<<<64, 512>>>(codebook);
    vq_main_kernel<<<HW_N / 128, 256>>>(z_e, codebook, out);
    vq_final_kernel<<<KN, DN>>>(ema_cs, ema_sum, out);
}

// round 8
// speedup vs baseline: 1.2282x; 1.2282x over previous
#include <cuda_runtime.h>
#include <cuda_bf16.h>

// Problem constants
#define HW_N   262144      // H*W
#define KN     512         // num_embeddings
#define DN     64          // embedding_dim
#define EMA_D  0.99f
#define EPS    1e-5f

// Output layout (reference return order, all fp32):
#define O_ZQ    0               // z_q_st   [H,W,D] 16777216
#define O_IDX   16777216        // indices  [H,W]     262144
#define O_MIND  17039360        // min_dist [N]       262144
#define O_CB    17301504        // new_codebook [K,D]  32768
#define O_CS    17334272        // new_ema_cluster [K]   512
#define O_SUM   17334784        // new_ema_emb_sum [K,D] 32768

// Scratch (no cudaMalloc allowed) — zeroed every launch by init kernel.
__device__ float g_counts[KN];
__device__ float g_sums[KN * DN];
__device__ float g_bsq[KN];

// packed fp32x2 FMA (SASS FFMA2) — 2x fp32 throughput (approx path only)
__device__ __forceinline__ unsigned long long fma2(unsigned long long a,
                                                   unsigned long long b,
                                                   unsigned long long c) {
    unsigned long long d;
    asm("fma.rn.f32x2 %0, %1, %2, %3;" : "=l"(d) : "l"(a), "l"(b), "l"(c));
    return d;
}

__device__ __forceinline__ float sum2(unsigned long long a) {
    unsigned int lo, hi;
    asm("mov.b64 {%0, %1}, %2;" : "=r"(lo), "=r"(hi) : "l"(a));
    return __uint_as_float(lo) + __uint_as_float(hi);
}

// ---------------------------------------------------------------------------
// Kernel 1: zero scratch + codebook squared norms (strict sequential order,
// matching the validated recheck arithmetic). 256 blocks for latency hiding.
// ---------------------------------------------------------------------------
__global__ void vq_init_kernel(const float* __restrict__ cb) {
    int t = blockIdx.x * 128 + threadIdx.x;   // 0..32767
    g_sums[t] = 0.0f;
    if (t < KN) {
        g_counts[t] = 0.0f;
        const float4* row = (const float4*)(cb + t * DN);
        float4 v[16];
#pragma unroll
        for (int i = 0; i < 16; i++) v[i] = row[i];   // MLP=16 loads
        float s = 0.0f;
#pragma unroll
        for (int i = 0; i < 16; i++) {                // strict sequential adds
            s = __fadd_rn(s, __fmul_rn(v[i].x, v[i].x));
            s = __fadd_rn(s, __fmul_rn(v[i].y, v[i].y));
            s = __fadd_rn(s, __fmul_rn(v[i].z, v[i].z));
            s = __fadd_rn(s, __fmul_rn(v[i].w, v[i].w));
        }
        g_bsq[t] = s;
    }
}

// ---------------------------------------------------------------------------
// Kernel 2: distances + top-2 argmin + exact recheck + z_q + EMA scatter
//   Block: 128 threads = 4 (k-lanes) x 32 (point-lanes). 256 points/block.
//   Microtile 8 points x 8 codes (f32x2 FMA) -> 1.0 B smem per lane-FMA,
//   balancing the 128 B/cyc crossbar against FFMA2 peak.
//   Codebook chunks of 32 through smem with register prefetch.
// ---------------------------------------------------------------------------
#define ZS 68   // smem row stride in floats (16B aligned, conflict-free)
#define NPB 256 // points per block
// dyn smem: z[256*68] c[32*68] asq[256] bsq[32] idx[256] c1[256] c2[256]
#define SMEM_BYTES ((NPB*ZS + 32*ZS + NPB + 32 + 3*NPB) * 4)

__global__ __launch_bounds__(128)
void vq_main_kernel(const float* __restrict__ z_e,
                    const float* __restrict__ cb,
                    float* __restrict__ out) {
    extern __shared__ float sm[];
    float* z_sm   = sm;                    // 256*68
    float* c_sm   = z_sm + NPB * ZS;       // 32*68
    float* asq_sm = c_sm + 32 * ZS;        // 256
    float* bsq_sm = asq_sm + NPB;          // 32
    int*   idx_sm = (int*)(bsq_sm + 32);   // 256
    int*   c1_sm  = idx_sm + NPB;          // 256
    int*   c2_sm  = c1_sm + NPB;           // 256

    const int tid = threadIdx.x;
    const int tx  = tid & 3;     // k-lane (0..3)
    const int ty  = tid >> 2;    // point-lane (0..31)
    const int pbase = blockIdx.x * NPB;

    // this thread's 4 float4 slots within a 32-row codebook chunk
    // slot s = tid + i*128, row = s>>4 (0..31), col4 = s&15

    // ---- load 256x64 z tile (4096 float4 slots, 32 per thread)
#pragma unroll
    for (int i = 0; i < 32; i++) {
        int e   = tid + i * 128;
        int row = e >> 4;
        int c4  = e & 15;
        float4 v = *(const float4*)(z_e + (size_t)(pbase + row) * DN + c4 * 4);
        *(float4*)&z_sm[row * ZS + c4 * 4] = v;
    }

    // ---- prefetch codebook chunk 0 (4 float4 per thread)
    float4 pf[4];
#pragma unroll
    for (int i = 0; i < 4; i++) {
        int s = tid + i * 128;
        pf[i] = *(const float4*)(cb + (size_t)(s >> 4) * DN + (s & 15) * 4);
    }
    float pfb = (tid < 32) ? g_bsq[tid] : 0.0f;

    __syncthreads();

    // ---- a_sq (2 points per thread), sequential rn(s + rn(v*v))
#pragma unroll
    for (int r = 0; r < 2; r++) {
        int p = tid + r * 128;
        float s = 0.0f;
#pragma unroll
        for (int d = 0; d < DN; d++) {
            float v = z_sm[p * ZS + d];
            s = __fadd_rn(s, __fmul_rn(v, v));
        }
        asq_sm[p] = s;
    }

    // top-2 tracking per point (approx values, index tie-break)
    float v1[8], v2[8];
    int   i1[8], i2[8];
#pragma unroll
    for (int pp = 0; pp < 8; pp++) {
        v1[pp] = 3.4e38f; v2[pp] = 3.4e38f; i1[pp] = KN; i2[pp] = KN;
    }

    for (int chunk = 0; chunk < KN / 32; chunk++) {
        // commit prefetched chunk to smem
#pragma unroll
        for (int i = 0; i < 4; i++) {
            int s = tid + i * 128;
            *(float4*)&c_sm[(s >> 4) * ZS + (s & 15) * 4] = pf[i];
        }
        if (tid < 32) bsq_sm[tid] = pfb;
        __syncthreads();

        // prefetch next chunk while this one is consumed
        if (chunk + 1 < KN / 32) {
            const float* cbn = cb + (size_t)(chunk + 1) * 32 * DN;
#pragma unroll
            for (int i = 0; i < 4; i++) {
                int s = tid + i * 128;
                pf[i] = *(const float4*)(cbn + (size_t)(s >> 4) * DN + (s & 15) * 4);
            }
            if (tid < 32) pfb = g_bsq[(chunk + 1) * 32 + tid];
        }

        unsigned long long acc[8][8];
#pragma unroll
        for (int pp = 0; pp < 8; pp++)
#pragma unroll
            for (int kk = 0; kk < 8; kk++) acc[pp][kk] = 0ULL;

#pragma unroll
        for (int d4 = 0; d4 < DN / 4; d4++) {
            ulonglong2 zv[8];
#pragma unroll
            for (int pp = 0; pp < 8; pp++)
                zv[pp] = *(const ulonglong2*)&z_sm[(pp * 32 + ty) * ZS + d4 * 4];
#pragma unroll
            for (int kk = 0; kk < 8; kk++) {
                ulonglong2 cv =
                    *(const ulonglong2*)&c_sm[(kk * 4 + tx) * ZS + d4 * 4];
#pragma unroll
                for (int pp = 0; pp < 8; pp++) {
                    acc[pp][kk] = fma2(zv[pp].x, cv.x, acc[pp][kk]);
                    acc[pp][kk] = fma2(zv[pp].y, cv.y, acc[pp][kk]);
                }
            }
        }

        // ---- top-2 update (approx vals; ascending k preserves ties-by-index)
#pragma unroll
        for (int kk = 0; kk < 8; kk++) {
            int kloc = kk * 4 + tx;
            int kg   = chunk * 32 + kloc;
            float b  = bsq_sm[kloc];
#pragma unroll
            for (int pp = 0; pp < 8; pp++) {
                float val = fmaf(-2.0f, sum2(acc[pp][kk]), b);
                if (val < v2[pp]) {
                    if (val < v1[pp]) {
                        v2[pp] = v1[pp]; i2[pp] = i1[pp];
                        v1[pp] = val;    i1[pp] = kg;
                    } else {
                        v2[pp] = val;    i2[pp] = kg;
                    }
                }
            }
        }
        __syncthreads();
    }

    // ---- merge top-2 across the 4 k-lanes (xor shuffles in 4-lane groups)
#pragma unroll
    for (int off = 2; off >= 1; off >>= 1) {
#pragma unroll
        for (int pp = 0; pp < 8; pp++) {
            float ov1 = __shfl_xor_sync(0xFFFFFFFFu, v1[pp], off);
            int   oi1 = __shfl_xor_sync(0xFFFFFFFFu, i1[pp], off);
            float ov2 = __shfl_xor_sync(0xFFFFFFFFu, v2[pp], off);
            int   oi2 = __shfl_xor_sync(0xFFFFFFFFu, i2[pp], off);
            if (ov1 < v1[pp] || (ov1 == v1[pp] && oi1 < i1[pp])) {
                float nv2; int ni2;
                if (v1[pp] < ov2 || (v1[pp] == ov2 && i1[pp] < oi2)) {
                    nv2 = v1[pp]; ni2 = i1[pp];
                } else { nv2 = ov2; ni2 = oi2; }
                v1[pp] = ov1; i1[pp] = oi1;
                v2[pp] = nv2; i2[pp] = ni2;
            } else if (ov1 < v2[pp] || (ov1 == v2[pp] && oi1 < i2[pp])) {
                v2[pp] = ov1; i2[pp] = oi1;
            }
        }
    }

    if (tx == 0) {
#pragma unroll
        for (int pp = 0; pp < 8; pp++) {
            int p = pp * 32 + ty;
            c1_sm[p] = i1[pp];
            c2_sm[p] = i2[pp];
        }
    }
    __syncthreads();

    // ---- exact recheck of the two finalists with reference arithmetic:
    //   dot = sequential-k single-accumulator fmaf chain
    //   val = rn(rn(a_sq - rn(2*dot)) + b_sq), ties -> lowest index
#pragma unroll
    for (int r = 0; r < 2; r++) {
        int p   = tid + r * 128;
        int ca  = c1_sm[p];
        int cb2 = c2_sm[p];
        float asq = asq_sm[p];
        const float* rowa = cb + (size_t)ca  * DN;
        const float* rowb = cb + (size_t)cb2 * DN;
        float da = 0.0f, db = 0.0f;
#pragma unroll
        for (int d = 0; d < DN; d++) {
            float z = z_sm[p * ZS + d];
            da = fmaf(z, __ldg(rowa + d), da);
            db = fmaf(z, __ldg(rowb + d), db);
        }
        float va = __fadd_rn(__fsub_rn(asq, __fmul_rn(2.0f, da)), g_bsq[ca]);
        float vb = __fadd_rn(__fsub_rn(asq, __fmul_rn(2.0f, db)), g_bsq[cb2]);
        int wi; float wv;
        if (vb < va || (vb == va && cb2 < ca)) { wi = cb2; wv = vb; }
        else                                    { wi = ca;  wv = va; }
        idx_sm[p] = wi;
        out[O_IDX  + pbase + p] = (float)wi;
        out[O_MIND + pbase + p] = wv;
        atomicAdd(&g_counts[wi], 1.0f);
    }
    __syncthreads();

    // ---- epilogue: z_q_st gather + embedding scatter-add (2 points/thread)
#pragma unroll
    for (int r = 0; r < 2; r++) {
        int p  = tid + r * 128;
        int ci = idx_sm[p];
        const float* crow = cb + (size_t)ci * DN;
        float* orow = out + O_ZQ + (size_t)(pbase + p) * DN;
        float* srow = g_sums + (size_t)ci * DN;
#pragma unroll
        for (int q = 0; q < 16; q++) {
            int d = q * 4;
            float4 c = *(const float4*)(crow + d);
            float4 z = *(const float4*)&z_sm[p * ZS + d];
            // straight-through: z + (z_q - z)  (match reference fp order)
            float4 rr;
            rr.x = __fadd_rn(z.x, __fsub_rn(c.x, z.x));
            rr.y = __fadd_rn(z.y, __fsub_rn(c.y, z.y));
            rr.z = __fadd_rn(z.z, __fsub_rn(c.z, z.z));
            rr.w = __fadd_rn(z.w, __fsub_rn(c.w, z.w));
            *(float4*)(orow + d) = rr;
            asm volatile("red.global.add.v4.f32 [%0], {%1, %2, %3, %4};"
                         :: "l"(srow + d), "f"(z.x), "f"(z.y), "f"(z.z), "f"(z.w)
                         : "memory");
        }
    }
}

// ---------------------------------------------------------------------------
// Kernel 3: EMA update + new codebook (exact rn ops)
// ---------------------------------------------------------------------------
__global__ void vq_final_kernel(const float* __restrict__ ema_cs,
                                const float* __restrict__ ema_sum,
                                float* __restrict__ out) {
    int k = blockIdx.x;      // 512 blocks
    int d = threadIdx.x;     // 64 threads
    float cs_new = __fadd_rn(__fmul_rn(EMA_D, ema_cs[k]),
                             __fmul_rn(1.0f - EMA_D, g_counts[k]));
    if (d == 0) out[O_CS + k] = cs_new;
    float s_new = __fadd_rn(__fmul_rn(EMA_D, ema_sum[k * DN + d]),
                            __fmul_rn(1.0f - EMA_D, g_sums[k * DN + d]));
    out[O_SUM + k * DN + d] = s_new;
    out[O_CB  + k * DN + d] = __fdiv_rn(s_new, __fadd_rn(cs_new, EPS));
}

// ---------------------------------------------------------------------------
extern "C" void kernel_launch(void* const* d_in, const int* in_sizes, int n_in,
                              void* d_out, int out_size) {
    const float* z_e      = (const float*)d_in[0];
    const float* codebook = (const float*)d_in[1];
    const float* ema_cs   = (const float*)d_in[2];
    const float* ema_sum  = (const float*)d_in[3];
    float* out = (float*)d_out;

    cudaFuncSetAttribute(vq_main_kernel,
                         cudaFuncAttributeMaxDynamicSharedMemorySize,
                         SMEM_BYTES);

    vq_init_kernel<<<256, 128>>>(codebook);
    vq_main_kernel<<<HW_N / NPB, 128, SMEM_BYTES>>>(z_e, codebook, out);
    vq_final_kernel<<<KN, DN>>>(ema_cs, ema_sum, out);
}